// round 11
// baseline (speedup 1.0000x reference)
#include <cuda_runtime.h>
#include <cuda_fp16.h>
#include <stdint.h>

#define IN_C    64
#define OUT_C   128
#define HWID    48
#define IMG     2304
#define IN_DIM  576
#define NROWS   36864
#define KTOT    5184
#define TM      128
#define KC      64
#define NCHUNK  81
#define NSILU   9
#define NT      256
#define ABUF    16384
#define METAOFF (4 * ABUF)
#define SMEM_TOTAL (4 * ABUF + 2048)

static __device__ __align__(16) __half g_Wt[OUT_C * KTOT];
static __device__ int g_conv;   // -1 dense fallback; else border*10 + type*2 + sel

// per-mm entry: 4 x 3b value selectors (0-3 = q[i], 7 = zero) | meta byte << 16
// (verified case-by-case against even/odd slot permutation)
#define ENT(s0,s1,s2,s3,m) ((uint32_t)((s0)|((s1)<<3)|((s2)<<6)|((s3)<<9)|((uint32_t)(m)<<16)))
static __device__ const uint32_t c_tab[12] = {
    ENT(3,7,7,7,0x44), ENT(2,7,3,7,0x44), ENT(1,3,2,7,0x44), ENT(0,2,1,3,0x44),
    ENT(1,3,0,2,0x49), ENT(0,2,1,3,0x99), ENT(1,3,0,2,0x9E), ENT(0,2,1,3,0xEE),
    ENT(7,1,0,2,0xEE), ENT(7,0,7,1,0xEE), ENT(7,7,7,0,0xE4), ENT(7,7,7,7,0x44)
};

template <int V> struct IC { static constexpr int value = V; };

__device__ __forceinline__ uint32_t smem_u32(const void* p) {
    uint32_t a;
    asm("{ .reg .u64 t; cvta.to.shared.u64 t, %1; cvt.u32.u64 %0, t; }" : "=r"(a) : "l"(p));
    return a;
}
__device__ __forceinline__ uint32_t sw_off(uint32_t o) { return o ^ ((o >> 3) & 0x70u); }
__device__ __forceinline__ void ldmx4(uint32_t r[4], uint32_t a) {
    asm volatile("ldmatrix.sync.aligned.m8n8.x4.shared.b16 {%0,%1,%2,%3}, [%4];"
                 : "=r"(r[0]), "=r"(r[1]), "=r"(r[2]), "=r"(r[3]) : "r"(a));
}
__device__ __forceinline__ void mma16816(float c[4], const uint32_t a[4],
                                         uint32_t b0, uint32_t b1) {
    asm volatile("mma.sync.aligned.m16n8k16.row.col.f32.f16.f16.f32 "
                 "{%0,%1,%2,%3}, {%4,%5,%6,%7}, {%8,%9}, {%0,%1,%2,%3};"
                 : "+f"(c[0]), "+f"(c[1]), "+f"(c[2]), "+f"(c[3])
                 : "r"(a[0]), "r"(a[1]), "r"(a[2]), "r"(a[3]), "r"(b0), "r"(b1));
}
template <int SEL>
__device__ __forceinline__ void mmasp(float c[4], const uint32_t a[4],
                                      uint32_t b0, uint32_t b1, uint32_t b2, uint32_t b3,
                                      uint32_t e) {
    asm volatile("mma.sp::ordered_metadata.sync.aligned.m16n8k32.row.col.f32.f16.f16.f32 "
                 "{%0,%1,%2,%3}, {%4,%5,%6,%7}, {%8,%9,%10,%11}, {%0,%1,%2,%3}, %12, %13;"
                 : "+f"(c[0]), "+f"(c[1]), "+f"(c[2]), "+f"(c[3])
                 : "r"(a[0]), "r"(a[1]), "r"(a[2]), "r"(a[3]),
                   "r"(b0), "r"(b1), "r"(b2), "r"(b3), "r"(e), "n"(SEL));
}

// ---------------- probe: discover mma.sp convention (1 warp, 20 candidates) ----------------
__global__ void probe_sparse() {
    __shared__ __align__(1024) char pA[2048];    // 16 rows x 128B, compressed A (16 fp16/row)
    __shared__ __align__(1024) char pB[2048];    // 8 n-rows x 128B (32 fp16 used)
    __shared__ uint32_t sMeta[16];
    __shared__ float sRef[128];
    __shared__ int sOk;
    const int lane = threadIdx.x;
    const int pr[6] = {0x4, 0x8, 0xC, 0x9, 0xD, 0xE};

    for (int i = lane; i < 512; i += 32) { ((uint32_t*)pA)[i] = 0; ((uint32_t*)pB)[i] = 0; }
    if (lane == 0) sOk = -1;
    __syncwarp();

    for (int idx = lane; idx < 256; idx += 32) {          // compressed A values
        int r = idx >> 4, q = idx & 15, g = q >> 1, eo = q & 1;
        float cv = 0.25f * (float)((r * 5 + g * 3 + eo * 7) % 11 - 5);
        *(__half*)(pA + sw_off((uint32_t)(r * 128 + q * 2))) = __float2half(cv);
    }
    if (lane < 16) {                                       // metadata words (nibble g = group g)
        uint32_t mw = 0;
        for (int g = 0; g < 8; ++g) mw |= (uint32_t)pr[(lane + g) % 6] << (4 * g);
        sMeta[lane] = mw;
    }
    for (int idx = lane; idx < 256; idx += 32) {           // dense B
        int n = idx >> 5, k = idx & 31;
        float bv = 0.25f * (float)((n * 7 + k * 3) % 9 - 4);
        *(__half*)(pB + sw_off((uint32_t)(n * 128 + k * 2))) = __float2half(bv);
    }
    __syncwarp();
    for (int oidx = lane; oidx < 128; oidx += 32) {        // reference D
        int r = oidx >> 3, n = oidx & 7;
        float s = 0.f;
        for (int g = 0; g < 8; ++g) {
            int nib = pr[(r + g) % 6];
            float c0 = 0.25f * (float)((r * 5 + g * 3) % 11 - 5);
            float c1 = 0.25f * (float)((r * 5 + g * 3 + 7) % 11 - 5);
            int k0 = 4 * g + (nib & 3), k1 = 4 * g + ((nib >> 2) & 3);
            s += c0 * (0.25f * (float)((n * 7 + k0 * 3) % 9 - 4));
            s += c1 * (0.25f * (float)((n * 7 + k1 * 3) % 9 - 4));
        }
        sRef[r * 8 + n] = s;
    }
    __syncwarp();

    const uint32_t aAb = smem_u32(pA), bBb = smem_u32(pB);
    uint32_t af[4], bL[4], bH[4];
    ldmx4(af, aAb + sw_off((uint32_t)((lane & 15) * 128 + (lane >> 4) * 16)));
    uint32_t brow = ((lane >> 4) << 3) + (lane & 7);
    uint32_t bko  = ((lane >> 3) & 1) * 16;
    ldmx4(bL, bBb + sw_off(brow * 128u + bko));            // k0-15
    ldmx4(bH, bBb + sw_off(brow * 128u + 32 + bko));       // k16-31
    const int myr = lane >> 2, myc = (lane & 3) * 2;
    const int r = lane >> 2, kb0 = lane & 1, kb1 = (lane >> 1) & 1;

    for (int conv = 0; conv < 20; ++conv) {
        int border = conv / 10, rem = conv % 10, t = rem >> 1, sel = conv & 1;
        uint32_t e;
        if (t == 0)      e = sMeta[r + 8 * kb0];
        else if (t == 1) e = sMeta[r + 8 * kb1];
        else if (t == 2) e = ((sMeta[r] >> (16 * kb0)) & 0xffffu) |
                             (((sMeta[r + 8] >> (16 * kb0)) & 0xffffu) << 16);
        else if (t == 3) e = ((sMeta[r] >> (16 * kb1)) & 0xffffu) |
                             (((sMeta[r + 8] >> (16 * kb1)) & 0xffffu) << 16);
        else             e = ((sMeta[r + 8] >> (16 * kb0)) & 0xffffu) |
                             (((sMeta[r] >> (16 * kb0)) & 0xffffu) << 16);
        uint32_t B1 = (border == 0) ? bL[1] : bH[0];
        uint32_t B2 = (border == 0) ? bH[0] : bL[1];
        float c[4] = {0.f, 0.f, 0.f, 0.f};
        if (sel == 0) mmasp<0>(c, af, bL[0], B1, B2, bH[1], e);
        else          mmasp<1>(c, af, bL[0], B1, B2, bH[1], e);
        bool ok = fabsf(c[0] - sRef[myr * 8 + myc])           < 0.01f &&
                  fabsf(c[1] - sRef[myr * 8 + myc + 1])       < 0.01f &&
                  fabsf(c[2] - sRef[(myr + 8) * 8 + myc])     < 0.01f &&
                  fabsf(c[3] - sRef[(myr + 8) * 8 + myc + 1]) < 0.01f;
        if (__all_sync(0xffffffffu, ok)) { if (lane == 0 && sOk < 0) sOk = conv; }
        __syncwarp();
    }
    if (lane == 0) g_conv = sOk;
}

// ---------------- weight packing (even/odd slot-permuted iff sparse) ----------------
__global__ void prep_weights(const float* __restrict__ Wb,
                             const float* __restrict__ Ws,
                             const float* __restrict__ Sc) {
    int idx = blockIdx.x * 256 + threadIdx.x;
    if (idx >= OUT_C * KTOT) return;
    int conv = g_conv;
    int o = idx / KTOT;
    int k = idx - o * KTOT;
    float v;
    if (k < IN_DIM) {
        v = Wb[o * IN_DIM + k];
    } else {
        int kk = k - IN_DIM;
        int d = kk >> 3, p = kk & 7;
        int j = (conv >= 0) ? (((p & 3) << 1) | (p >> 2)) : p;
        v = Ws[(o * IN_DIM + d) * 8 + j] * Sc[o * IN_DIM + d];
    }
    g_Wt[idx] = __float2half(v);
}

// ---------------- main fused kernel ----------------
__global__ void __launch_bounds__(NT, 2)
convkan_mma(const float* __restrict__ xg, float* __restrict__ outg) {
    extern __shared__ char dsm[];    // [A0|A1|B0|B1] + meta0(1K)|meta1(1K)
    __shared__ int s_cb[TM], s_lb[TM], s_khw[TM];
    __shared__ uint32_t s_tab[12];

    const uint32_t sbase = smem_u32(dsm);
    const uint32_t sB = sbase + 2 * ABUF;
    const int tid  = threadIdx.x;
    const int wid  = tid >> 5;
    const int lane = tid & 31;
    const int row_base = blockIdx.x * TM;
    const int conv = g_conv;

    if (tid < TM) {
        int n  = row_base + tid;
        int b  = n / IMG;
        int nl = n - b * IMG;
        int i0 = nl >> 2;
        int cc = i0 / 9;
        int t9 = i0 - cc * 9;
        int kh = t9 / 3;
        s_cb[tid]  = (b * IN_C + cc) * IMG;
        s_lb[tid]  = (nl & 3) * IN_DIM;
        s_khw[tid] = (kh << 8) | (t9 - kh * 3);
    }
    if (tid < 12) s_tab[tid] = c_tab[tid];
    __syncthreads();

    const int dlc = tid & 7, mbase = tid >> 3;
    int sp_hh[4], sp_w[4], sp_cb[4], sp_kw[4];
    #pragma unroll
    for (int it = 0; it < 4; ++it) {
        int m  = mbase + 32 * it;
        int l0 = s_lb[m] + dlc;
        int h  = l0 / HWID;
        sp_w[it]  = l0 - h * HWID;
        sp_hh[it] = h + ((s_khw[m] >> 8) - 1);
        sp_cb[it] = s_cb[m];
        sp_kw[it] = (s_khw[m] & 255) - 1;
    }
    float xv[4];

    auto prefetch_spline = [&]() {
        #pragma unroll
        for (int it = 0; it < 4; ++it) {
            int hh = sp_hh[it], w = sp_w[it];
            int ww = w + sp_kw[it];
            float v = 0.f;
            if (((unsigned)hh < (unsigned)HWID) && ((unsigned)ww < (unsigned)HWID))
                v = __ldg(xg + sp_cb[it] + hh * HWID + ww);
            xv[it] = v;
            w += 8;
            if (w >= HWID) { w -= HWID; hh += 1; }
            sp_w[it] = w; sp_hh[it] = hh;
        }
    };

    auto store_spline_d = [&](uint32_t Abase) {
        #pragma unroll
        for (int it = 0; it < 4; ++it) {
            float v = xv[it];
            float sv = fmaf(v, 2.5f, 5.5f);
            float fm = floorf(sv);
            float f = sv - fm, f2 = f * f, f3 = f2 * f;
            float omf = 1.f - f;
            unsigned short q[4];
            q[0] = __half_as_ushort(__float2half_rn((1.f / 6.f) * omf * omf * omf));
            q[1] = __half_as_ushort(__float2half_rn(0.5f * f3 - f2 + (2.f / 3.f)));
            q[2] = __half_as_ushort(__float2half_rn((1.f / 6.f) + 0.5f * (f + f2 - f3)));
            q[3] = __half_as_ushort(__float2half_rn((1.f / 6.f) * f3));
            int t0 = (int)fm - 3;
            uint32_t addr = Abase + sw_off((uint32_t)((mbase + 32 * it) * 128 + dlc * 16));
            asm volatile("st.shared.v4.b32 [%0], {%1,%1,%1,%1};" :: "r"(addr), "r"(0u) : "memory");
            #pragma unroll
            for (int i = 0; i < 4; ++i) {
                int j = t0 + i;
                if ((unsigned)j < 8u)
                    asm volatile("st.shared.b16 [%0], %1;"
                                 :: "r"(addr + (uint32_t)(j * 2)), "h"(q[i]) : "memory");
            }
        }
    };

    auto store_spline_sp = [&](uint32_t Abase, uint32_t Mbase) {
        #pragma unroll
        for (int it = 0; it < 4; ++it) {
            float v = xv[it];
            float sv = fmaf(v, 2.5f, 5.5f);
            float fm = floorf(sv);
            float f = sv - fm, f2 = f * f, f3 = f2 * f;
            float omf = 1.f - f;
            float q0 = (1.f / 6.f) * omf * omf * omf;
            float q1 = 0.5f * f3 - f2 + (2.f / 3.f);
            float q2 = (1.f / 6.f) + 0.5f * (f + f2 - f3);
            float q3 = (1.f / 6.f) * f3;
            int mm = (int)fm;
            if ((unsigned)mm > 10u) mm = 11;
            uint32_t entry = s_tab[mm];
            auto pick = [&](int sb) {
                return sb == 0 ? q0 : sb == 1 ? q1 : sb == 2 ? q2 : sb == 3 ? q3 : 0.f;
            };
            __half2 hlo = __floats2half2_rn(pick(entry & 7), pick((entry >> 3) & 7));
            __half2 hhi = __floats2half2_rn(pick((entry >> 6) & 7), pick((entry >> 9) & 7));
            int m = mbase + 32 * it;
            uint32_t addr = Abase + sw_off((uint32_t)(m * 128 + dlc * 8));
            asm volatile("st.shared.v2.b32 [%0], {%1,%2};"
                         :: "r"(addr), "r"(*(uint32_t*)&hlo), "r"(*(uint32_t*)&hhi) : "memory");
            asm volatile("st.shared.b8 [%0], %1;"
                         :: "r"(Mbase + (uint32_t)(m * 8 + dlc)), "r"(entry >> 16) : "memory");
        }
    };

    auto gen_silu = [&](uint32_t Abase, int chunk) {
        const int d0 = chunk * KC;
        #pragma unroll
        for (int it = 0; it < 2; ++it) {
            int e = tid + NT * it;
            int g = e & 3, m = e >> 2;
            int cb = s_cb[m], khw = s_khw[m];
            int khm1 = (khw >> 8) - 1, kwm1 = (khw & 255) - 1;
            int l0 = s_lb[m] + d0 + g * 16;
            int h0 = l0 / HWID;
            int w0 = l0 - h0 * HWID;
            uint32_t hv[8];
            #pragma unroll
            for (int j = 0; j < 16; j += 2) {
                float vv[2];
                #pragma unroll
                for (int q = 0; q < 2; ++q) {
                    int w = w0 + j + q, h = h0;
                    if (w >= HWID) { w -= HWID; h += 1; }
                    int hh = h + khm1, ww = w + kwm1;
                    float v = 0.f;
                    if (((unsigned)hh < (unsigned)HWID) && ((unsigned)ww < (unsigned)HWID))
                        v = __ldg(xg + cb + hh * HWID + ww);
                    vv[q] = __fdividef(v, 1.f + __expf(-v));
                }
                __half2 h2 = __floats2half2_rn(vv[0], vv[1]);
                hv[j >> 1] = *reinterpret_cast<uint32_t*>(&h2);
            }
            uint32_t a0 = Abase + sw_off((uint32_t)(m * 128 + g * 32));
            uint32_t a1 = Abase + sw_off((uint32_t)(m * 128 + g * 32 + 16));
            asm volatile("st.shared.v4.b32 [%0], {%1,%2,%3,%4};"
                         :: "r"(a0), "r"(hv[0]), "r"(hv[1]), "r"(hv[2]), "r"(hv[3]) : "memory");
            asm volatile("st.shared.v4.b32 [%0], {%1,%2,%3,%4};"
                         :: "r"(a1), "r"(hv[4]), "r"(hv[5]), "r"(hv[6]), "r"(hv[7]) : "memory");
        }
    };

    auto fill_b = [&](uint32_t Bb, int chunk) {
        const __half* wsrc = g_Wt + chunk * KC;
        #pragma unroll
        for (int it = 0; it < 4; ++it) {
            int s = tid + NT * it;
            int o = s >> 3, seg = s & 7;
            uint32_t dst = Bb + sw_off((uint32_t)(o * 128 + seg * 16));
            const void* src = (const void*)(wsrc + (size_t)o * KTOT + seg * 8);
            asm volatile("cp.async.cg.shared.global [%0], [%1], 16;" :: "r"(dst), "l"(src));
        }
        asm volatile("cp.async.commit_group;" ::: "memory");
    };

    fill_b(sB, 0);
    gen_silu(sbase, 0);

    float acc[2][8][4];
    #pragma unroll
    for (int mi = 0; mi < 2; ++mi)
        #pragma unroll
        for (int nb = 0; nb < 8; ++nb)
            #pragma unroll
            for (int q = 0; q < 4; ++q) acc[mi][nb][q] = 0.f;

    const int wm = (wid & 3) * 32;
    const int wn = (wid >> 2) * 64;
    const uint32_t a_row  = wm + (lane & 15);
    const uint32_t a_koff = (lane >> 4) * 16;
    const uint32_t b_row  = wn + ((lane >> 4) << 3) + (lane & 7);
    const uint32_t b_koff = ((lane >> 3) & 1) * 16;

    // precompute metadata addressing per discovered convention
    uint32_t offA[2] = {0, 0}, offB[2] = {0, 0};
    bool meta32 = true;
    if (conv >= 0) {
        int t = (conv % 10) >> 1;
        meta32 = (t <= 1);
        int kb0 = lane & 1, kb1 = (lane >> 1) & 1;
        #pragma unroll
        for (int mi = 0; mi < 2; ++mi) {
            int r = wm + mi * 16 + (lane >> 2);
            if (t == 0)      offA[mi] = (uint32_t)((r + 8 * kb0) * 8);
            else if (t == 1) offA[mi] = (uint32_t)((r + 8 * kb1) * 8);
            else if (t == 2) { offA[mi] = (uint32_t)(r * 8 + kb0 * 2);
                               offB[mi] = (uint32_t)((r + 8) * 8 + kb0 * 2); }
            else if (t == 3) { offA[mi] = (uint32_t)(r * 8 + kb1 * 2);
                               offB[mi] = (uint32_t)((r + 8) * 8 + kb1 * 2); }
            else             { offA[mi] = (uint32_t)((r + 8) * 8 + kb0 * 2);
                               offB[mi] = (uint32_t)(r * 8 + kb0 * 2); }
        }
    }

    auto dense_step = [&](uint32_t aB, uint32_t bB) {
        #pragma unroll
        for (int ks = 0; ks < 4; ++ks) {
            const uint32_t kb = ks * 32;
            uint32_t af[2][4];
            ldmx4(af[0], aB + sw_off(a_row * 128u + kb + a_koff));
            ldmx4(af[1], aB + sw_off((a_row + 16) * 128u + kb + a_koff));
            uint32_t bf[4][4];
            #pragma unroll
            for (int g = 0; g < 4; ++g)
                ldmx4(bf[g], bB + sw_off((b_row + g * 16) * 128u + kb + b_koff));
            #pragma unroll
            for (int mi = 0; mi < 2; ++mi)
                #pragma unroll
                for (int nb = 0; nb < 8; ++nb)
                    mma16816(acc[mi][nb], af[mi],
                             bf[nb >> 1][(nb & 1) * 2], bf[nb >> 1][(nb & 1) * 2 + 1]);
        }
    };

    auto sparse_step = [&](uint32_t aB, uint32_t bB, uint32_t metab, auto selc, auto bordc) {
        constexpr int S  = decltype(selc)::value;
        constexpr int BO = decltype(bordc)::value;
        #pragma unroll
        for (int ks = 0; ks < 2; ++ks) {
            uint32_t af[2][4];
            #pragma unroll
            for (int mi = 0; mi < 2; ++mi)
                ldmx4(af[mi], aB + sw_off((a_row + mi * 16) * 128u + ks * 32 + a_koff));
            uint32_t bA[4][4], bC[4][4];
            #pragma unroll
            for (int g = 0; g < 4; ++g) {
                ldmx4(bA[g], bB + sw_off((b_row + g * 16) * 128u + ks * 64 + b_koff));
                ldmx4(bC[g], bB + sw_off((b_row + g * 16) * 128u + ks * 64 + 32 + b_koff));
            }
            uint32_t e[2];
            #pragma unroll
            for (int mi = 0; mi < 2; ++mi) {
                if (meta32) {
                    asm volatile("ld.shared.b32 %0, [%1];" : "=r"(e[mi])
                                 : "r"(metab + offA[mi] + (uint32_t)(ks * 4)));
                } else {
                    uint32_t lo, hi;
                    asm volatile("ld.shared.u16 %0, [%1];" : "=r"(lo)
                                 : "r"(metab + offA[mi] + (uint32_t)(ks * 4)));
                    asm volatile("ld.shared.u16 %0, [%1];" : "=r"(hi)
                                 : "r"(metab + offB[mi] + (uint32_t)(ks * 4)));
                    e[mi] = lo | (hi << 16);
                }
            }
            #pragma unroll
            for (int mi = 0; mi < 2; ++mi)
                #pragma unroll
                for (int nb = 0; nb < 8; ++nb) {
                    int g = nb >> 1, j2 = (nb & 1) * 2;
                    uint32_t P1 = (BO == 0) ? bA[g][j2 + 1] : bC[g][j2];
                    uint32_t P2 = (BO == 0) ? bC[g][j2]     : bA[g][j2 + 1];
                    mmasp<S>(acc[mi][nb], af[mi], bA[g][j2], P1, P2, bC[g][j2 + 1], e[mi]);
                }
        }
    };

    for (int c = 0; c < NCHUNK; ++c) {
        const int buf = c & 1;
        const bool havenext = (c + 1 < NCHUNK);
        if (havenext) {
            fill_b(sB + (buf ^ 1) * ABUF, c + 1);
            if (c + 1 >= NSILU) prefetch_spline();
            asm volatile("cp.async.wait_group 1;" ::: "memory");
        } else {
            asm volatile("cp.async.wait_group 0;" ::: "memory");
        }
        __syncthreads();

        const uint32_t aB = sbase + buf * ABUF;
        const uint32_t bB = sB + buf * ABUF;
        const uint32_t metab = sbase + METAOFF + buf * 1024;
        if (c < NSILU || conv < 0) dense_step(aB, bB);
        else {
            int dcase = (conv >= 10) * 2 + (conv & 1);
            if (dcase == 0)      sparse_step(aB, bB, metab, IC<0>{}, IC<0>{});
            else if (dcase == 1) sparse_step(aB, bB, metab, IC<1>{}, IC<0>{});
            else if (dcase == 2) sparse_step(aB, bB, metab, IC<0>{}, IC<1>{});
            else                 sparse_step(aB, bB, metab, IC<1>{}, IC<1>{});
        }

        if (havenext) {
            if (c + 1 < NSILU)  gen_silu(sbase + (buf ^ 1) * ABUF, c + 1);
            else if (conv >= 0) store_spline_sp(sbase + (buf ^ 1) * ABUF,
                                                sbase + METAOFF + (buf ^ 1) * 1024);
            else                store_spline_d(sbase + (buf ^ 1) * ABUF);
        }
        __syncthreads();
    }

    #pragma unroll
    for (int mi = 0; mi < 2; ++mi) {
        int r0 = row_base + wm + mi * 16 + (lane >> 2);
        float* p0 = outg + (size_t)r0 * OUT_C + wn + (lane & 3) * 2;
        float* p1 = p0 + 8 * OUT_C;
        #pragma unroll
        for (int nb = 0; nb < 8; ++nb) {
            *(float2*)(p0 + nb * 8) = make_float2(acc[mi][nb][0], acc[mi][nb][1]);
            *(float2*)(p1 + nb * 8) = make_float2(acc[mi][nb][2], acc[mi][nb][3]);
        }
    }
}

extern "C" void kernel_launch(void* const* d_in, const int* in_sizes, int n_in,
                              void* d_out, int out_size) {
    const float* x  = (const float*)d_in[0];
    const float* wb = (const float*)d_in[1];
    const float* ws = (const float*)d_in[2];
    const float* sc = (const float*)d_in[3];
    float* out = (float*)d_out;

    cudaFuncSetAttribute(convkan_mma, cudaFuncAttributeMaxDynamicSharedMemorySize, SMEM_TOTAL);
    probe_sparse<<<1, 32>>>();
    prep_weights<<<(OUT_C * KTOT + 255) / 256, 256>>>(wb, ws, sc);
    convkan_mma<<<NROWS / TM, NT, SMEM_TOTAL>>>(x, out);
}

// round 12
// speedup vs baseline: 2.0541x; 2.0541x over previous
#include <cuda_runtime.h>
#include <cuda_fp16.h>
#include <stdint.h>

#define IN_C    64
#define OUT_C   128
#define HWID    48
#define IMG     2304
#define IN_DIM  576
#define NROWS   36864
#define KTOT    5184
#define TM      128
#define KC      64
#define NCHUNK  81
#define NSILU   9
#define NT      256
#define ABUF    16384
#define NSTG    3
#define SMEM_TOTAL (2 * NSTG * ABUF)   // 96 KB: A ring (3) + B ring (3)

static __device__ __align__(16) __half g_Wt[OUT_C * KTOT];

// ---------------- weight packing: Wt[o][k], k<576 -> base, else spline*scaler ----
__global__ void prep_weights(const float* __restrict__ Wb,
                             const float* __restrict__ Ws,
                             const float* __restrict__ Sc) {
    int idx = blockIdx.x * 256 + threadIdx.x;
    if (idx >= OUT_C * KTOT) return;
    int o = idx / KTOT;
    int k = idx - o * KTOT;
    float v;
    if (k < IN_DIM) {
        v = Wb[o * IN_DIM + k];
    } else {
        int kk = k - IN_DIM;
        int d = kk >> 3, j = kk & 7;
        v = Ws[(o * IN_DIM + d) * 8 + j] * Sc[o * IN_DIM + d];
    }
    g_Wt[idx] = __float2half(v);
}

// ---------------- helpers ----------------
__device__ __forceinline__ uint32_t smem_u32(const void* p) {
    uint32_t a;
    asm("{ .reg .u64 t; cvta.to.shared.u64 t, %1; cvt.u32.u64 %0, t; }" : "=r"(a) : "l"(p));
    return a;
}
__device__ __forceinline__ uint32_t sw_off(uint32_t o) { return o ^ ((o >> 3) & 0x70u); }

__device__ __forceinline__ void ldmx4(uint32_t r[4], uint32_t a) {
    asm volatile("ldmatrix.sync.aligned.m8n8.x4.shared.b16 {%0,%1,%2,%3}, [%4];"
                 : "=r"(r[0]), "=r"(r[1]), "=r"(r[2]), "=r"(r[3]) : "r"(a));
}
__device__ __forceinline__ void mma16816(float c[4], const uint32_t a[4],
                                         uint32_t b0, uint32_t b1) {
    asm volatile("mma.sync.aligned.m16n8k16.row.col.f32.f16.f16.f32 "
                 "{%0,%1,%2,%3}, {%4,%5,%6,%7}, {%8,%9}, {%0,%1,%2,%3};"
                 : "+f"(c[0]), "+f"(c[1]), "+f"(c[2]), "+f"(c[3])
                 : "r"(a[0]), "r"(a[1]), "r"(a[2]), "r"(a[3]), "r"(b0), "r"(b1));
}

// ---------------- main fused HMMA kernel: 3-stage ring, ONE sync per chunk ----------------
__global__ void __launch_bounds__(NT, 2)
convkan_mma(const float* __restrict__ xg, float* __restrict__ outg) {
    extern __shared__ char dsm[];                 // [A0|A1|A2 | B0|B1|B2]
    __shared__ int s_cb[TM], s_lb[TM], s_khw[TM];

    const uint32_t sbase = smem_u32(dsm);
    const uint32_t sB = sbase + NSTG * ABUF;
    const int tid  = threadIdx.x;
    const int wid  = tid >> 5;
    const int lane = tid & 31;
    const int row_base = blockIdx.x * TM;

    if (tid < TM) {
        int n  = row_base + tid;
        int b  = n / IMG;
        int nl = n - b * IMG;
        int i0 = nl >> 2;
        int cc = i0 / 9;
        int t9 = i0 - cc * 9;
        int kh = t9 / 3;
        s_cb[tid]  = (b * IN_C + cc) * IMG;
        s_lb[tid]  = (nl & 3) * IN_DIM;
        s_khw[tid] = (kh << 8) | (t9 - kh * 3);
    }
    __syncthreads();

    // ---- persistent incremental coords for spline chunks (4 elems/thread) ----
    const int dlc = tid & 7, mbase = tid >> 3;
    int sp_hh[4], sp_w[4], sp_cb[4], sp_kw[4];
    #pragma unroll
    for (int it = 0; it < 4; ++it) {
        int m  = mbase + 32 * it;
        int l0 = s_lb[m] + dlc;
        int h  = l0 / HWID;
        sp_w[it]  = l0 - h * HWID;
        sp_hh[it] = h + ((s_khw[m] >> 8) - 1);
        sp_cb[it] = s_cb[m];
        sp_kw[it] = (s_khw[m] & 255) - 1;
    }
    float xv[4];

    auto prefetch_spline = [&]() {
        #pragma unroll
        for (int it = 0; it < 4; ++it) {
            int hh = sp_hh[it], w = sp_w[it];
            int ww = w + sp_kw[it];
            float v = 0.f;
            if (((unsigned)hh < (unsigned)HWID) && ((unsigned)ww < (unsigned)HWID))
                v = __ldg(xg + sp_cb[it] + hh * HWID + ww);
            xv[it] = v;
            w += 8;
            if (w >= HWID) { w -= HWID; hh += 1; }
            sp_w[it] = w; sp_hh[it] = hh;
        }
    };

    auto store_spline = [&](uint32_t Abase) {
        #pragma unroll
        for (int it = 0; it < 4; ++it) {
            float v = xv[it];
            // cardinal cubic B-spline, uniform extended grid (h=0.4, lo=-1)
            float sv = fmaf(v, 2.5f, 5.5f);
            float fm = floorf(sv);
            float f = sv - fm, f2 = f * f, f3 = f2 * f;
            float omf = 1.f - f;
            unsigned short q[4];
            q[0] = __half_as_ushort(__float2half_rn((1.f / 6.f) * omf * omf * omf));
            q[1] = __half_as_ushort(__float2half_rn(0.5f * f3 - f2 + (2.f / 3.f)));
            q[2] = __half_as_ushort(__float2half_rn((1.f / 6.f) + 0.5f * (f + f2 - f3)));
            q[3] = __half_as_ushort(__float2half_rn((1.f / 6.f) * f3));
            int t0 = (int)fm - 3;
            uint32_t addr = Abase + sw_off((uint32_t)((mbase + 32 * it) * 128 + dlc * 16));
            asm volatile("st.shared.v4.b32 [%0], {%1,%1,%1,%1};" :: "r"(addr), "r"(0u) : "memory");
            #pragma unroll
            for (int i = 0; i < 4; ++i) {
                int j = t0 + i;
                if ((unsigned)j < 8u)
                    asm volatile("st.shared.b16 [%0], %1;"
                                 :: "r"(addr + (uint32_t)(j * 2)), "h"(q[i]) : "memory");
            }
        }
    };

    auto gen_silu = [&](uint32_t Abase, int chunk) {
        const int d0 = chunk * KC;
        #pragma unroll
        for (int it = 0; it < 2; ++it) {
            int e = tid + NT * it;
            int g = e & 3, m = e >> 2;
            int cb = s_cb[m], khw = s_khw[m];
            int khm1 = (khw >> 8) - 1, kwm1 = (khw & 255) - 1;
            int l0 = s_lb[m] + d0 + g * 16;
            int h0 = l0 / HWID;
            int w0 = l0 - h0 * HWID;
            uint32_t hv[8];
            #pragma unroll
            for (int j = 0; j < 16; j += 2) {
                float vv[2];
                #pragma unroll
                for (int q = 0; q < 2; ++q) {
                    int w = w0 + j + q, h = h0;
                    if (w >= HWID) { w -= HWID; h += 1; }
                    int hh = h + khm1, ww = w + kwm1;
                    float v = 0.f;
                    if (((unsigned)hh < (unsigned)HWID) && ((unsigned)ww < (unsigned)HWID))
                        v = __ldg(xg + cb + hh * HWID + ww);
                    vv[q] = __fdividef(v, 1.f + __expf(-v));
                }
                __half2 h2 = __floats2half2_rn(vv[0], vv[1]);
                hv[j >> 1] = *reinterpret_cast<uint32_t*>(&h2);
            }
            uint32_t a0 = Abase + sw_off((uint32_t)(m * 128 + g * 32));
            uint32_t a1 = Abase + sw_off((uint32_t)(m * 128 + g * 32 + 16));
            asm volatile("st.shared.v4.b32 [%0], {%1,%2,%3,%4};"
                         :: "r"(a0), "r"(hv[0]), "r"(hv[1]), "r"(hv[2]), "r"(hv[3]) : "memory");
            asm volatile("st.shared.v4.b32 [%0], {%1,%2,%3,%4};"
                         :: "r"(a1), "r"(hv[4]), "r"(hv[5]), "r"(hv[6]), "r"(hv[7]) : "memory");
        }
    };

    auto fill_b = [&](uint32_t Bb, int chunk) {
        const __half* wsrc = g_Wt + chunk * KC;
        #pragma unroll
        for (int it = 0; it < 4; ++it) {
            int s = tid + NT * it;
            int o = s >> 3, seg = s & 7;
            uint32_t dst = Bb + sw_off((uint32_t)(o * 128 + seg * 16));
            const void* src = (const void*)(wsrc + (size_t)o * KTOT + seg * 8);
            asm volatile("cp.async.cg.shared.global [%0], [%1], 16;" :: "r"(dst), "l"(src));
        }
        asm volatile("cp.async.commit_group;" ::: "memory");
    };

    // ---- prologue: stage chunk 0 ----
    fill_b(sB, 0);
    gen_silu(sbase, 0);

    float acc[2][8][4];
    #pragma unroll
    for (int mi = 0; mi < 2; ++mi)
        #pragma unroll
        for (int nb = 0; nb < 8; ++nb)
            #pragma unroll
            for (int q = 0; q < 4; ++q) acc[mi][nb][q] = 0.f;

    const int wm = (wid & 3) * 32;
    const int wn = (wid >> 2) * 64;
    const uint32_t a_row  = wm + (lane & 15);
    const uint32_t a_koff = (lane >> 4) * 16;
    const uint32_t b_row  = wn + ((lane >> 4) << 3) + (lane & 7);
    const uint32_t b_koff = ((lane >> 3) & 1) * 16;

    int stg = 0, stg_n = 1;                       // c % 3, (c+1) % 3
    for (int c = 0; c < NCHUNK; ++c) {
        const bool havenext = (c + 1 < NCHUNK);
        if (havenext) {
            fill_b(sB + stg_n * ABUF, c + 1);     // B(c+1) cp.async (independent of sync)
            if (c + 1 >= NSILU) prefetch_spline();
            asm volatile("cp.async.wait_group 1;" ::: "memory");   // B(c) complete
        } else {
            asm volatile("cp.async.wait_group 0;" ::: "memory");
        }
        __syncthreads();   // SINGLE barrier: orders A(c) writes (iter c-1) before reads,
                           // and read(c-2) of slot stg_n before its rewrite below

        const uint32_t aB = sbase + stg * ABUF;
        const uint32_t bB = sB + stg * ABUF;
        #pragma unroll
        for (int ks = 0; ks < 4; ++ks) {
            const uint32_t kb = ks * 32;
            uint32_t af[2][4];
            ldmx4(af[0], aB + sw_off(a_row * 128u + kb + a_koff));
            ldmx4(af[1], aB + sw_off((a_row + 16) * 128u + kb + a_koff));
            uint32_t bf[4][4];
            #pragma unroll
            for (int g = 0; g < 4; ++g)
                ldmx4(bf[g], bB + sw_off((b_row + g * 16) * 128u + kb + b_koff));
            #pragma unroll
            for (int mi = 0; mi < 2; ++mi)
                #pragma unroll
                for (int nb = 0; nb < 8; ++nb)
                    mma16816(acc[mi][nb], af[mi],
                             bf[nb >> 1][(nb & 1) * 2], bf[nb >> 1][(nb & 1) * 2 + 1]);
        }

        // produce A(c+1) into ring slot stg_n (visible to consumers after next barrier)
        if (havenext) {
            if (c + 1 < NSILU) gen_silu(sbase + stg_n * ABUF, c + 1);
            else               store_spline(sbase + stg_n * ABUF);
        }
        stg = stg_n;
        stg_n = (stg_n == NSTG - 1) ? 0 : stg_n + 1;
    }

    // epilogue: C[n, o] -> out[n*128 + o] (flat reinterpret of (16,128,48,48))
    #pragma unroll
    for (int mi = 0; mi < 2; ++mi) {
        int r0 = row_base + wm + mi * 16 + (lane >> 2);
        float* p0 = outg + (size_t)r0 * OUT_C + wn + (lane & 3) * 2;
        float* p1 = p0 + 8 * OUT_C;
        #pragma unroll
        for (int nb = 0; nb < 8; ++nb) {
            *(float2*)(p0 + nb * 8) = make_float2(acc[mi][nb][0], acc[mi][nb][1]);
            *(float2*)(p1 + nb * 8) = make_float2(acc[mi][nb][2], acc[mi][nb][3]);
        }
    }
}

extern "C" void kernel_launch(void* const* d_in, const int* in_sizes, int n_in,
                              void* d_out, int out_size) {
    const float* x  = (const float*)d_in[0];   // (16, 64, 48, 48)
    const float* wb = (const float*)d_in[1];   // (128, 576)
    const float* ws = (const float*)d_in[2];   // (128, 576, 8)
    const float* sc = (const float*)d_in[3];   // (128, 576)
    float* out = (float*)d_out;                // flat (36864, 128)

    cudaFuncSetAttribute(convkan_mma, cudaFuncAttributeMaxDynamicSharedMemorySize, SMEM_TOTAL);
    prep_weights<<<(OUT_C * KTOT + 255) / 256, 256>>>(wb, ws, sc);
    convkan_mma<<<NROWS / TM, NT, SMEM_TOTAL>>>(x, out);
}